// round 6
// baseline (speedup 1.0000x reference)
#include <cuda_runtime.h>
#include <cuda_bf16.h>
#include <cstdint>

#define BATCH 4
#define CH    512
#define HW    4096
#define AD    512

typedef __nv_bfloat16 bf16;

// ---------------- scratch (__device__ globals; no allocation) ---------------
__device__ bf16 g_qh[BATCH * HW * AD];
__device__ bf16 g_ql[BATCH * HW * AD];
__device__ bf16 g_kh[BATCH * HW * AD];
__device__ bf16 g_kl[BATCH * HW * AD];
__device__ bf16 g_vth[BATCH * CH * HW];   // v transposed: [b][c][n]
__device__ bf16 g_vtl[BATCH * CH * HW];
__device__ float g_S[(size_t)BATCH * HW * HW];   // scores fp32
__device__ bf16 g_ph[(size_t)BATCH * HW * HW];   // softmax probs hi/lo
__device__ bf16 g_pl[(size_t)BATCH * HW * HW];

// ---------------- helpers ----------------------------------------------------
__device__ __forceinline__ uint32_t smem_u32(const void* p) {
    uint32_t a;
    asm("{ .reg .u64 t; cvta.to.shared.u64 t, %1; cvt.u32.u64 %0, t; }" : "=r"(a) : "l"(p));
    return a;
}
__device__ __forceinline__ void cp16(uint32_t d, const void* s) {
    asm volatile("cp.async.ca.shared.global [%0], [%1], 16;" :: "r"(d), "l"(s));
}
__device__ __forceinline__ void cp_commit() { asm volatile("cp.async.commit_group;" ::: "memory"); }
__device__ __forceinline__ void cp_wait2()  { asm volatile("cp.async.wait_group 2;" ::: "memory"); }

__device__ __forceinline__ uint32_t lds32(const bf16* base, int halfoff) {
    return *reinterpret_cast<const uint32_t*>(base + halfoff);
}

__device__ __forceinline__ void mma16816(float* c,
    uint32_t a0, uint32_t a1, uint32_t a2, uint32_t a3, uint32_t b0, uint32_t b1)
{
    asm volatile(
        "mma.sync.aligned.m16n8k16.row.col.f32.bf16.bf16.f32 "
        "{%0,%1,%2,%3},{%4,%5,%6,%7},{%8,%9},{%0,%1,%2,%3};"
        : "+f"(c[0]), "+f"(c[1]), "+f"(c[2]), "+f"(c[3])
        : "r"(a0), "r"(a1), "r"(a2), "r"(a3), "r"(b0), "r"(b1));
}

// FMA-only exp (x <= 0)
__device__ __forceinline__ float fast_exp_neg(float x) {
    float t = x * 1.4426950408889634f;
    t = fmaxf(t, -126.0f);
    float r = rintf(t);
    float f = t - r;
    float p = 1.3333558e-3f;
    p = fmaf(p, f, 9.6181291e-3f);
    p = fmaf(p, f, 5.5504110e-2f);
    p = fmaf(p, f, 2.4022651e-1f);
    p = fmaf(p, f, 6.9314718e-1f);
    p = fmaf(p, f, 1.0f);
    return __int_as_float(__float_as_int(p) + ((int)r << 23));
}

__device__ __forceinline__ void split2(float v, bf16& h, bf16& l) {
    h = __float2bfloat16(v);
    l = __float2bfloat16(v - __bfloat162float(h));
}

// ---------------- smem layout: K=16 stages, 4-deep circular pipeline ---------
// 4 tiles (Ah, Al, Bh, Bl): 128 rows x 16 halves, row stride 24 halves (48B,
// conflict-free for the A-frag and B-frag lane patterns; proven in R3).
#define TT      24
#define TILE_H  3072            // 128*24 halves
#define TILE_B  6144
#define STAGE_H 12288           // 4 tiles
#define STAGE_B 24576
#define NSTAGE  4
#define SMEM_GEMM (NSTAGE * STAGE_B)   // 98304 -> 2 CTA/SM (196.6KB of 228KB)

__device__ __forceinline__ void stage_load16(uint32_t sb, int st,
    const bf16* __restrict__ Ah, const bf16* __restrict__ Al,
    const bf16* __restrict__ Bh, const bf16* __restrict__ Bl,
    int ldA, int ldB, int k0, int tid)
{
    int row = tid >> 1;
    int ho  = (tid & 1) * 8;
    uint32_t d = sb + st * STAGE_B + row * 48 + (tid & 1) * 16;
    const size_t oA = (size_t)row * ldA + k0 + ho;
    const size_t oB = (size_t)row * ldB + k0 + ho;
    cp16(d + 0 * TILE_B, Ah + oA);
    cp16(d + 1 * TILE_B, Al + oA);
    cp16(d + 2 * TILE_B, Bh + oB);
    cp16(d + 3 * TILE_B, Bl + oB);
    cp_commit();
}

__device__ __forceinline__ void stage_mma16(const bf16* smst, float acc[4][4][4],
                                            int wm, int wn, int g, int tg)
{
    const bf16* sAh = smst;
    const bf16* sAl = smst + TILE_H;
    const bf16* sBh = smst + 2 * TILE_H;
    const bf16* sBl = smst + 3 * TILE_H;

    uint32_t ah[4][4], bh[4][2];
    #pragma unroll
    for (int i = 0; i < 4; i++) {
        int r = wm * 64 + i * 16 + g;
        ah[i][0] = lds32(sAh, r * TT + tg * 2);
        ah[i][1] = lds32(sAh, (r + 8) * TT + tg * 2);
        ah[i][2] = lds32(sAh, r * TT + tg * 2 + 8);
        ah[i][3] = lds32(sAh, (r + 8) * TT + tg * 2 + 8);
    }
    #pragma unroll
    for (int j = 0; j < 4; j++) {
        int r = wn * 32 + j * 8 + g;
        bh[j][0] = lds32(sBh, r * TT + tg * 2);
        bh[j][1] = lds32(sBh, r * TT + tg * 2 + 8);
    }
    #pragma unroll
    for (int i = 0; i < 4; i++)
        #pragma unroll
        for (int j = 0; j < 4; j++)
            mma16816(acc[i][j], ah[i][0], ah[i][1], ah[i][2], ah[i][3], bh[j][0], bh[j][1]);

    uint32_t bl[4][2];
    #pragma unroll
    for (int j = 0; j < 4; j++) {
        int r = wn * 32 + j * 8 + g;
        bl[j][0] = lds32(sBl, r * TT + tg * 2);
        bl[j][1] = lds32(sBl, r * TT + tg * 2 + 8);
    }
    #pragma unroll
    for (int i = 0; i < 4; i++)
        #pragma unroll
        for (int j = 0; j < 4; j++)
            mma16816(acc[i][j], ah[i][0], ah[i][1], ah[i][2], ah[i][3], bl[j][0], bl[j][1]);

    uint32_t al[4][4];
    #pragma unroll
    for (int i = 0; i < 4; i++) {
        int r = wm * 64 + i * 16 + g;
        al[i][0] = lds32(sAl, r * TT + tg * 2);
        al[i][1] = lds32(sAl, (r + 8) * TT + tg * 2);
        al[i][2] = lds32(sAl, r * TT + tg * 2 + 8);
        al[i][3] = lds32(sAl, (r + 8) * TT + tg * 2 + 8);
    }
    #pragma unroll
    for (int i = 0; i < 4; i++)
        #pragma unroll
        for (int j = 0; j < 4; j++)
            mma16816(acc[i][j], al[i][0], al[i][1], al[i][2], al[i][3], bh[j][0], bh[j][1]);
}

#define MMA_PROLOG()                                                             \
    extern __shared__ char smc[];                                                \
    bf16* sm = reinterpret_cast<bf16*>(smc);                                     \
    uint32_t sb = smem_u32(smc);                                                 \
    int tid = threadIdx.x, lane = tid & 31, wid = tid >> 5;                      \
    int wm = wid & 1, wn = wid >> 1, g = lane >> 2, tg = lane & 3;               \
    float acc[4][4][4];                                                          \
    _Pragma("unroll")                                                            \
    for (int i = 0; i < 4; i++)                                                  \
        _Pragma("unroll")                                                        \
        for (int j = 0; j < 4; j++)                                              \
            _Pragma("unroll")                                                    \
            for (int r = 0; r < 4; r++) acc[i][j][r] = 0.f;

// 4-stage circular pipeline, one barrier per stage, wait_group 2.
// Empty commit at the tail keeps group accounting exact (wait_group counts
// groups, so every iteration must retire exactly one).
#define MMA_MAINLOOP(Ah, Al, Bh, Bl, ldA, ldB, KS)                               \
    stage_load16(sb, 0, Ah, Al, Bh, Bl, ldA, ldB, 0, tid);                       \
    stage_load16(sb, 1, Ah, Al, Bh, Bl, ldA, ldB, 16, tid);                      \
    stage_load16(sb, 2, Ah, Al, Bh, Bl, ldA, ldB, 32, tid);                      \
    for (int s = 0; s < (KS); s++) {                                             \
        cp_wait2();                                                              \
        __syncthreads();                                                         \
        if (s + 3 < (KS))                                                        \
            stage_load16(sb, (s + 3) & 3, Ah, Al, Bh, Bl, ldA, ldB,              \
                         (s + 3) * 16, tid);                                     \
        else                                                                     \
            cp_commit();                                                         \
        stage_mma16(sm + (s & 3) * STAGE_H, acc, wm, wn, g, tg);                 \
    }

// ---------------------------------------------------------------------------
// K1: fused projections (fp32 CUDA-core GEMM), emits bf16 hi/lo splits.
// q,k: [n][a] (a contiguous). v: transposed [c][n] (n contiguous).
// ---------------------------------------------------------------------------
#define BM 128
#define BN 128
#define BKK 16

__global__ __launch_bounds__(256, 2) void k_proj(
    const float* __restrict__ x,
    const float* __restrict__ Wq, const float* __restrict__ bq,
    const float* __restrict__ Wk, const float* __restrict__ bk,
    const float* __restrict__ Wv, const float* __restrict__ bv)
{
    int z = blockIdx.z;
    int b = z / 3, p = z % 3;
    const float* W    = (p == 0) ? Wq : ((p == 1) ? Wk : Wv);
    const float* bias = (p == 0) ? bq : ((p == 1) ? bk : bv);
    const float* X = x + (size_t)b * CH * HW;

    int n0 = blockIdx.x * BM;
    int a0 = blockIdx.y * BN;

    __shared__ float As[BKK][BM + 4];
    __shared__ float Bs[BKK][BN + 4];

    int tid = threadIdx.x;
    int tx = tid & 15, ty = tid >> 4;
    int r8 = tid >> 5, c4 = tid & 31;
    int lr = tid >> 2, lq = tid & 3;

    float acc[8][8];
    #pragma unroll
    for (int i = 0; i < 8; i++)
        #pragma unroll
        for (int j = 0; j < 8; j++) acc[i][j] = 0.f;

    for (int c0 = 0; c0 < CH; c0 += BKK) {
        #pragma unroll
        for (int s = 0; s < 2; s++) {
            int kr = r8 + s * 8;
            float4 t = *reinterpret_cast<const float4*>(&X[(size_t)(c0 + kr) * HW + n0 + c4 * 4]);
            *reinterpret_cast<float4*>(&As[kr][c4 * 4]) = t;
        }
        #pragma unroll
        for (int s = 0; s < 2; s++) {
            int nn = lr + s * 64;
            float4 t = *reinterpret_cast<const float4*>(&W[(size_t)(a0 + nn) * CH + c0 + lq * 4]);
            Bs[lq * 4 + 0][nn] = t.x; Bs[lq * 4 + 1][nn] = t.y;
            Bs[lq * 4 + 2][nn] = t.z; Bs[lq * 4 + 3][nn] = t.w;
        }
        __syncthreads();
        #pragma unroll
        for (int kk = 0; kk < BKK; kk++) {
            float ra[8], rb[8];
            #pragma unroll
            for (int i = 0; i < 8; i++) ra[i] = As[kk][ty * 8 + i];
            #pragma unroll
            for (int j = 0; j < 8; j++) rb[j] = Bs[kk][tx * 8 + j];
            #pragma unroll
            for (int i = 0; i < 8; i++)
                #pragma unroll
                for (int j = 0; j < 8; j++)
                    acc[i][j] = fmaf(ra[i], rb[j], acc[i][j]);
        }
        __syncthreads();
    }

    float bb[8];
    #pragma unroll
    for (int j = 0; j < 8; j++) bb[j] = bias[a0 + tx * 8 + j];

    if (p < 2) {
        bf16* Yh = ((p == 0) ? g_qh : g_kh) + (size_t)b * HW * AD;
        bf16* Yl = ((p == 0) ? g_ql : g_kl) + (size_t)b * HW * AD;
        #pragma unroll
        for (int i = 0; i < 8; i++) {
            int n = n0 + ty * 8 + i;
            __align__(16) bf16 h8[8], l8[8];
            #pragma unroll
            for (int j = 0; j < 8; j++) {
                float val = acc[i][j] + bb[j];
                split2(val, h8[j], l8[j]);
            }
            size_t off = (size_t)n * AD + a0 + tx * 8;
            *reinterpret_cast<float4*>(&Yh[off]) = *reinterpret_cast<const float4*>(h8);
            *reinterpret_cast<float4*>(&Yl[off]) = *reinterpret_cast<const float4*>(l8);
        }
    } else {
        bf16* Th = g_vth + (size_t)b * CH * HW;
        bf16* Tl = g_vtl + (size_t)b * CH * HW;
        #pragma unroll
        for (int j = 0; j < 8; j++) {
            int c = a0 + tx * 8 + j;
            __align__(16) bf16 h8[8], l8[8];
            #pragma unroll
            for (int i = 0; i < 8; i++) {
                float val = acc[i][j] + bb[j];
                split2(val, h8[i], l8[i]);
            }
            size_t off = (size_t)c * HW + n0 + ty * 8;
            *reinterpret_cast<float4*>(&Th[off]) = *reinterpret_cast<const float4*>(h8);
            *reinterpret_cast<float4*>(&Tl[off]) = *reinterpret_cast<const float4*>(l8);
        }
    }
}

// ---------------------------------------------------------------------------
// K2: S = Q K^T (split, 3 products). Tile 128x128, K=512 (32 stages of 16).
// ---------------------------------------------------------------------------
__global__ __launch_bounds__(256) void k_scores_mma()
{
    MMA_PROLOG();
    int b = blockIdx.z;
    int m0 = blockIdx.x * 128;   // key block (cols)
    int n0 = blockIdx.y * 128;   // query block (rows)

    const bf16* Ah = g_qh + ((size_t)b * HW + n0) * AD;
    const bf16* Al = g_ql + ((size_t)b * HW + n0) * AD;
    const bf16* Bh = g_kh + ((size_t)b * HW + m0) * AD;
    const bf16* Bl = g_kl + ((size_t)b * HW + m0) * AD;

    MMA_MAINLOOP(Ah, Al, Bh, Bl, AD, AD, AD / 16);

    float* Sb = g_S + (size_t)b * HW * HW;
    #pragma unroll
    for (int i = 0; i < 4; i++) {
        int n = n0 + wm * 64 + i * 16 + g;
        #pragma unroll
        for (int j = 0; j < 4; j++) {
            int m = m0 + wn * 32 + j * 8 + tg * 2;
            *reinterpret_cast<float2*>(&Sb[(size_t)n * HW + m]) =
                make_float2(acc[i][j][0], acc[i][j][1]);
            *reinterpret_cast<float2*>(&Sb[(size_t)(n + 8) * HW + m]) =
                make_float2(acc[i][j][2], acc[i][j][3]);
        }
    }
}

// ---------------------------------------------------------------------------
// K3: column softmax (axis=-2); reads S fp32, writes P hi/lo bf16 splits.
// ---------------------------------------------------------------------------
__global__ __launch_bounds__(256) void k_softmax()
{
    int b = blockIdx.y;
    int col = threadIdx.x & 63;
    int m = blockIdx.x * 64 + col;
    int rq = threadIdx.x >> 6;
    const float* Sb = g_S + (size_t)b * HW * HW;
    bf16* Ph = g_ph + (size_t)b * HW * HW;
    bf16* Pl = g_pl + (size_t)b * HW * HW;

    int nbeg = rq * (HW / 4), nend = nbeg + (HW / 4);

    float mx = -3.4e38f, den = 0.f;
    for (int n = nbeg; n < nend; n += 8) {
        float v[8];
        #pragma unroll
        for (int u = 0; u < 8; u++) v[u] = Sb[(size_t)(n + u) * HW + m];
        #pragma unroll
        for (int u = 0; u < 8; u++) {
            float val = v[u];
            if (val > mx) { den = den * fast_exp_neg(mx - val) + 1.0f; mx = val; }
            else          { den += fast_exp_neg(val - mx); }
        }
    }

    __shared__ float smx[256], sden[256];
    __shared__ float cmx[64], cinv[64];
    smx[threadIdx.x] = mx; sden[threadIdx.x] = den;
    __syncthreads();
    if (threadIdx.x < 64) {
        float M = smx[threadIdx.x], D = sden[threadIdx.x];
        #pragma unroll
        for (int k = 1; k < 4; k++) {
            float m2 = smx[threadIdx.x + 64 * k], d2 = sden[threadIdx.x + 64 * k];
            float nm = fmaxf(M, m2);
            D = D * fast_exp_neg(M - nm) + d2 * fast_exp_neg(m2 - nm);
            M = nm;
        }
        cmx[threadIdx.x] = M;
        cinv[threadIdx.x] = 1.0f / D;
    }
    __syncthreads();
    float M = cmx[col], inv = cinv[col];

    for (int n = nbeg; n < nend; n += 8) {
        float v[8];
        #pragma unroll
        for (int u = 0; u < 8; u++) v[u] = Sb[(size_t)(n + u) * HW + m];
        #pragma unroll
        for (int u = 0; u < 8; u++) {
            float pv = fast_exp_neg(v[u] - M) * inv;
            bf16 h, l; split2(pv, h, l);
            Ph[(size_t)(n + u) * HW + m] = h;
            Pl[(size_t)(n + u) * HW + m] = l;
        }
    }
}

// ---------------------------------------------------------------------------
// K4: O = P V (split, 3 products) + residual. Tile 128(n) x 128(c), K=4096.
// ---------------------------------------------------------------------------
__global__ __launch_bounds__(256) void k_out_mma(
    const float* __restrict__ x, float* __restrict__ out)
{
    MMA_PROLOG();
    int b = blockIdx.z;
    int c0 = blockIdx.x * 128;
    int n0 = blockIdx.y * 128;

    const bf16* Ah = g_ph + (size_t)b * HW * HW + (size_t)n0 * HW;
    const bf16* Al = g_pl + (size_t)b * HW * HW + (size_t)n0 * HW;
    const bf16* Bh = g_vth + ((size_t)b * CH + c0) * HW;
    const bf16* Bl = g_vtl + ((size_t)b * CH + c0) * HW;

    MMA_MAINLOOP(Ah, Al, Bh, Bl, HW, HW, HW / 16);

    const float* xb = x + (size_t)b * CH * HW;
    float* ob = out + (size_t)b * CH * HW;
    #pragma unroll
    for (int i = 0; i < 4; i++) {
        int n = n0 + wm * 64 + i * 16 + g;
        #pragma unroll
        for (int j = 0; j < 4; j++) {
            int c = c0 + wn * 32 + j * 8 + tg * 2;
            {
                size_t off = (size_t)n * CH + c;
                float2 xv = *reinterpret_cast<const float2*>(&xb[off]);
                *reinterpret_cast<float2*>(&ob[off]) =
                    make_float2(fmaf(0.1f, acc[i][j][0], xv.x),
                                fmaf(0.1f, acc[i][j][1], xv.y));
            }
            {
                size_t off = (size_t)(n + 8) * CH + c;
                float2 xv = *reinterpret_cast<const float2*>(&xb[off]);
                *reinterpret_cast<float2*>(&ob[off]) =
                    make_float2(fmaf(0.1f, acc[i][j][2], xv.x),
                                fmaf(0.1f, acc[i][j][3], xv.y));
            }
        }
    }
}

// ---------------------------------------------------------------------------
extern "C" void kernel_launch(void* const* d_in, const int* in_sizes, int n_in,
                              void* d_out, int out_size)
{
    const float* x  = (const float*)d_in[0];
    const float* Wq = (const float*)d_in[1];
    const float* bq = (const float*)d_in[2];
    const float* Wk = (const float*)d_in[3];
    const float* bk = (const float*)d_in[4];
    const float* Wv = (const float*)d_in[5];
    const float* bv = (const float*)d_in[6];
    float* out = (float*)d_out;

    static int configured = 0;
    if (!configured) {
        cudaFuncSetAttribute(k_scores_mma, cudaFuncAttributeMaxDynamicSharedMemorySize, SMEM_GEMM);
        cudaFuncSetAttribute(k_out_mma,    cudaFuncAttributeMaxDynamicSharedMemorySize, SMEM_GEMM);
        configured = 1;
    }

    k_proj      <<<dim3(HW / BM, AD / BN, BATCH * 3), 256>>>(x, Wq, bq, Wk, bk, Wv, bv);
    k_scores_mma<<<dim3(HW / 128, HW / 128, BATCH), 256, SMEM_GEMM>>>();
    k_softmax   <<<dim3(HW / 64, BATCH), 256>>>();
    k_out_mma   <<<dim3(CH / 128, HW / 128, BATCH), 256, SMEM_GEMM>>>(x, out);
}

// round 7
// speedup vs baseline: 1.3851x; 1.3851x over previous
#include <cuda_runtime.h>
#include <cuda_bf16.h>
#include <cuda_fp16.h>
#include <cstdint>

#define BATCH 4
#define CH    512
#define HW    4096
#define AD    512

typedef __nv_bfloat16 bf16;

// ---------------- scratch (__device__ globals; no allocation) ---------------
__device__ bf16 g_qh[BATCH * HW * AD];
__device__ bf16 g_ql[BATCH * HW * AD];
__device__ bf16 g_kh[BATCH * HW * AD];
__device__ bf16 g_kl[BATCH * HW * AD];
__device__ __half g_vt16[BATCH * CH * HW];       // v transposed [b][c][n], fp16
__device__ float g_S[(size_t)BATCH * HW * HW];   // scores fp32
__device__ __half g_p16[(size_t)BATCH * HW * HW]; // softmax probs fp16

// ---------------- helpers ----------------------------------------------------
__device__ __forceinline__ uint32_t smem_u32(const void* p) {
    uint32_t a;
    asm("{ .reg .u64 t; cvta.to.shared.u64 t, %1; cvt.u32.u64 %0, t; }" : "=r"(a) : "l"(p));
    return a;
}
__device__ __forceinline__ void cp16(uint32_t d, const void* s) {
    asm volatile("cp.async.ca.shared.global [%0], [%1], 16;" :: "r"(d), "l"(s));
}
__device__ __forceinline__ void cp_commit() { asm volatile("cp.async.commit_group;" ::: "memory"); }
__device__ __forceinline__ void cp_wait0()  { asm volatile("cp.async.wait_group 0;" ::: "memory"); }
__device__ __forceinline__ void cp_wait2()  { asm volatile("cp.async.wait_group 2;" ::: "memory"); }

__device__ __forceinline__ uint32_t lds32(const bf16* base, int halfoff) {
    return *reinterpret_cast<const uint32_t*>(base + halfoff);
}
__device__ __forceinline__ uint32_t lds32h(const __half* base, int halfoff) {
    return *reinterpret_cast<const uint32_t*>(base + halfoff);
}

__device__ __forceinline__ void mma16816(float* c,
    uint32_t a0, uint32_t a1, uint32_t a2, uint32_t a3, uint32_t b0, uint32_t b1)
{
    asm volatile(
        "mma.sync.aligned.m16n8k16.row.col.f32.bf16.bf16.f32 "
        "{%0,%1,%2,%3},{%4,%5,%6,%7},{%8,%9},{%0,%1,%2,%3};"
        : "+f"(c[0]), "+f"(c[1]), "+f"(c[2]), "+f"(c[3])
        : "r"(a0), "r"(a1), "r"(a2), "r"(a3), "r"(b0), "r"(b1));
}
__device__ __forceinline__ void mma16816h(float* c,
    uint32_t a0, uint32_t a1, uint32_t a2, uint32_t a3, uint32_t b0, uint32_t b1)
{
    asm volatile(
        "mma.sync.aligned.m16n8k16.row.col.f32.f16.f16.f32 "
        "{%0,%1,%2,%3},{%4,%5,%6,%7},{%8,%9},{%0,%1,%2,%3};"
        : "+f"(c[0]), "+f"(c[1]), "+f"(c[2]), "+f"(c[3])
        : "r"(a0), "r"(a1), "r"(a2), "r"(a3), "r"(b0), "r"(b1));
}

// FMA-only exp (x <= 0)
__device__ __forceinline__ float fast_exp_neg(float x) {
    float t = x * 1.4426950408889634f;
    t = fmaxf(t, -126.0f);
    float r = rintf(t);
    float f = t - r;
    float p = 1.3333558e-3f;
    p = fmaf(p, f, 9.6181291e-3f);
    p = fmaf(p, f, 5.5504110e-2f);
    p = fmaf(p, f, 2.4022651e-1f);
    p = fmaf(p, f, 6.9314718e-1f);
    p = fmaf(p, f, 1.0f);
    return __int_as_float(__float_as_int(p) + ((int)r << 23));
}

__device__ __forceinline__ void split2(float v, bf16& h, bf16& l) {
    h = __float2bfloat16(v);
    l = __float2bfloat16(v - __bfloat162float(h));
}

// ---------------- scores smem layout: K=32 stages, double-buffered -----------
#define TT      40
#define TILE_H  5120
#define TILE_B  10240
#define STAGE_H 20480
#define STAGE_B 40960
#define SMEM_GEMM (2 * STAGE_B)   // 81920

__device__ __forceinline__ void stage_load32(uint32_t sb, int st,
    const bf16* __restrict__ Ah, const bf16* __restrict__ Al,
    const bf16* __restrict__ Bh, const bf16* __restrict__ Bl,
    int ldA, int ldB, int k0, int tid)
{
    int row = tid >> 1;
    int h0  = (tid & 1) * 16;
    uint32_t d = sb + st * STAGE_B + row * 80 + h0 * 2;
    const size_t oA = (size_t)row * ldA + k0 + h0;
    const size_t oB = (size_t)row * ldB + k0 + h0;
    cp16(d + 0 * TILE_B,      Ah + oA); cp16(d + 0 * TILE_B + 16, Ah + oA + 8);
    cp16(d + 1 * TILE_B,      Al + oA); cp16(d + 1 * TILE_B + 16, Al + oA + 8);
    cp16(d + 2 * TILE_B,      Bh + oB); cp16(d + 2 * TILE_B + 16, Bh + oB + 8);
    cp16(d + 3 * TILE_B,      Bl + oB); cp16(d + 3 * TILE_B + 16, Bl + oB + 8);
    cp_commit();
}

__device__ __forceinline__ void stage_mma32(const bf16* smst, float acc[4][4][4],
                                            int wm, int wn, int g, int tg)
{
    const bf16* sAh = smst;
    const bf16* sAl = smst + TILE_H;
    const bf16* sBh = smst + 2 * TILE_H;
    const bf16* sBl = smst + 3 * TILE_H;

    #pragma unroll
    for (int kh = 0; kh < 2; kh++) {
        int ko = kh * 16;
        uint32_t ah[4][4], bh[4][2];
        #pragma unroll
        for (int i = 0; i < 4; i++) {
            int r = wm * 64 + i * 16 + g;
            ah[i][0] = lds32(sAh, r * TT + ko + tg * 2);
            ah[i][1] = lds32(sAh, (r + 8) * TT + ko + tg * 2);
            ah[i][2] = lds32(sAh, r * TT + ko + tg * 2 + 8);
            ah[i][3] = lds32(sAh, (r + 8) * TT + ko + tg * 2 + 8);
        }
        #pragma unroll
        for (int j = 0; j < 4; j++) {
            int r = wn * 32 + j * 8 + g;
            bh[j][0] = lds32(sBh, r * TT + ko + tg * 2);
            bh[j][1] = lds32(sBh, r * TT + ko + tg * 2 + 8);
        }
        #pragma unroll
        for (int i = 0; i < 4; i++)
            #pragma unroll
            for (int j = 0; j < 4; j++)
                mma16816(acc[i][j], ah[i][0], ah[i][1], ah[i][2], ah[i][3], bh[j][0], bh[j][1]);

        uint32_t bl[4][2];
        #pragma unroll
        for (int j = 0; j < 4; j++) {
            int r = wn * 32 + j * 8 + g;
            bl[j][0] = lds32(sBl, r * TT + ko + tg * 2);
            bl[j][1] = lds32(sBl, r * TT + ko + tg * 2 + 8);
        }
        #pragma unroll
        for (int i = 0; i < 4; i++)
            #pragma unroll
            for (int j = 0; j < 4; j++)
                mma16816(acc[i][j], ah[i][0], ah[i][1], ah[i][2], ah[i][3], bl[j][0], bl[j][1]);

        uint32_t al[4][4];
        #pragma unroll
        for (int i = 0; i < 4; i++) {
            int r = wm * 64 + i * 16 + g;
            al[i][0] = lds32(sAl, r * TT + ko + tg * 2);
            al[i][1] = lds32(sAl, (r + 8) * TT + ko + tg * 2);
            al[i][2] = lds32(sAl, r * TT + ko + tg * 2 + 8);
            al[i][3] = lds32(sAl, (r + 8) * TT + ko + tg * 2 + 8);
        }
        #pragma unroll
        for (int i = 0; i < 4; i++)
            #pragma unroll
            for (int j = 0; j < 4; j++)
                mma16816(acc[i][j], al[i][0], al[i][1], al[i][2], al[i][3], bh[j][0], bh[j][1]);
    }
}

#define MMA_PROLOG()                                                             \
    extern __shared__ char smc[];                                                \
    uint32_t sb = smem_u32(smc);                                                 \
    int tid = threadIdx.x, lane = tid & 31, wid = tid >> 5;                      \
    int wm = wid & 1, wn = wid >> 1, g = lane >> 2, tg = lane & 3;               \
    float acc[4][4][4];                                                          \
    _Pragma("unroll")                                                            \
    for (int i = 0; i < 4; i++)                                                  \
        _Pragma("unroll")                                                        \
        for (int j = 0; j < 4; j++)                                              \
            _Pragma("unroll")                                                    \
            for (int r = 0; r < 4; r++) acc[i][j][r] = 0.f;

// ---------------- k_out smem layout: fp16, 2 tiles, 4-deep pipeline ----------
#define OT_TILE_H  5120          // 128 * 40 halves
#define OT_TILE_B  10240
#define OT_STAGE_H 10240         // 2 tiles
#define OT_STAGE_B 20480
#define OT_SMEM    (4 * OT_STAGE_B)   // 81920 -> 2 CTA/SM

__device__ __forceinline__ void stage_load_o(uint32_t sb, int st,
    const __half* __restrict__ A, const __half* __restrict__ B,
    int ldA, int ldB, int k0, int tid)
{
    int row = tid >> 1;
    int h0  = (tid & 1) * 16;
    uint32_t d = sb + st * OT_STAGE_B + row * 80 + h0 * 2;
    const size_t oA = (size_t)row * ldA + k0 + h0;
    const size_t oB = (size_t)row * ldB + k0 + h0;
    cp16(d,                  A + oA); cp16(d + 16,              A + oA + 8);
    cp16(d + OT_TILE_B,      B + oB); cp16(d + OT_TILE_B + 16,  B + oB + 8);
    cp_commit();
}

__device__ __forceinline__ void stage_mma_o(const __half* smst, float acc[4][4][4],
                                            int wm, int wn, int g, int tg)
{
    const __half* sA = smst;
    const __half* sB = smst + OT_TILE_H;

    #pragma unroll
    for (int kh = 0; kh < 2; kh++) {
        int ko = kh * 16;
        uint32_t a[4][4], b[4][2];
        #pragma unroll
        for (int i = 0; i < 4; i++) {
            int r = wm * 64 + i * 16 + g;
            a[i][0] = lds32h(sA, r * TT + ko + tg * 2);
            a[i][1] = lds32h(sA, (r + 8) * TT + ko + tg * 2);
            a[i][2] = lds32h(sA, r * TT + ko + tg * 2 + 8);
            a[i][3] = lds32h(sA, (r + 8) * TT + ko + tg * 2 + 8);
        }
        #pragma unroll
        for (int j = 0; j < 4; j++) {
            int r = wn * 32 + j * 8 + g;
            b[j][0] = lds32h(sB, r * TT + ko + tg * 2);
            b[j][1] = lds32h(sB, r * TT + ko + tg * 2 + 8);
        }
        #pragma unroll
        for (int i = 0; i < 4; i++)
            #pragma unroll
            for (int j = 0; j < 4; j++)
                mma16816h(acc[i][j], a[i][0], a[i][1], a[i][2], a[i][3], b[j][0], b[j][1]);
    }
}

// ---------------------------------------------------------------------------
// K1: fused projections (fp32 CUDA-core GEMM), emits bf16 splits (q,k) and
// fp16 transposed v.
// ---------------------------------------------------------------------------
#define BM 128
#define BN 128
#define BKK 16

__global__ __launch_bounds__(256, 2) void k_proj(
    const float* __restrict__ x,
    const float* __restrict__ Wq, const float* __restrict__ bq,
    const float* __restrict__ Wk, const float* __restrict__ bk,
    const float* __restrict__ Wv, const float* __restrict__ bv)
{
    int z = blockIdx.z;
    int b = z / 3, p = z % 3;
    const float* W    = (p == 0) ? Wq : ((p == 1) ? Wk : Wv);
    const float* bias = (p == 0) ? bq : ((p == 1) ? bk : bv);
    const float* X = x + (size_t)b * CH * HW;

    int n0 = blockIdx.x * BM;
    int a0 = blockIdx.y * BN;

    __shared__ float As[BKK][BM + 4];
    __shared__ float Bs[BKK][BN + 4];

    int tid = threadIdx.x;
    int tx = tid & 15, ty = tid >> 4;
    int r8 = tid >> 5, c4 = tid & 31;
    int lr = tid >> 2, lq = tid & 3;

    float acc[8][8];
    #pragma unroll
    for (int i = 0; i < 8; i++)
        #pragma unroll
        for (int j = 0; j < 8; j++) acc[i][j] = 0.f;

    for (int c0 = 0; c0 < CH; c0 += BKK) {
        #pragma unroll
        for (int s = 0; s < 2; s++) {
            int kr = r8 + s * 8;
            float4 t = *reinterpret_cast<const float4*>(&X[(size_t)(c0 + kr) * HW + n0 + c4 * 4]);
            *reinterpret_cast<float4*>(&As[kr][c4 * 4]) = t;
        }
        #pragma unroll
        for (int s = 0; s < 2; s++) {
            int nn = lr + s * 64;
            float4 t = *reinterpret_cast<const float4*>(&W[(size_t)(a0 + nn) * CH + c0 + lq * 4]);
            Bs[lq * 4 + 0][nn] = t.x; Bs[lq * 4 + 1][nn] = t.y;
            Bs[lq * 4 + 2][nn] = t.z; Bs[lq * 4 + 3][nn] = t.w;
        }
        __syncthreads();
        #pragma unroll
        for (int kk = 0; kk < BKK; kk++) {
            float ra[8], rb[8];
            #pragma unroll
            for (int i = 0; i < 8; i++) ra[i] = As[kk][ty * 8 + i];
            #pragma unroll
            for (int j = 0; j < 8; j++) rb[j] = Bs[kk][tx * 8 + j];
            #pragma unroll
            for (int i = 0; i < 8; i++)
                #pragma unroll
                for (int j = 0; j < 8; j++)
                    acc[i][j] = fmaf(ra[i], rb[j], acc[i][j]);
        }
        __syncthreads();
    }

    float bb[8];
    #pragma unroll
    for (int j = 0; j < 8; j++) bb[j] = bias[a0 + tx * 8 + j];

    if (p < 2) {
        bf16* Yh = ((p == 0) ? g_qh : g_kh) + (size_t)b * HW * AD;
        bf16* Yl = ((p == 0) ? g_ql : g_kl) + (size_t)b * HW * AD;
        #pragma unroll
        for (int i = 0; i < 8; i++) {
            int n = n0 + ty * 8 + i;
            __align__(16) bf16 h8[8], l8[8];
            #pragma unroll
            for (int j = 0; j < 8; j++) {
                float val = acc[i][j] + bb[j];
                split2(val, h8[j], l8[j]);
            }
            size_t off = (size_t)n * AD + a0 + tx * 8;
            *reinterpret_cast<float4*>(&Yh[off]) = *reinterpret_cast<const float4*>(h8);
            *reinterpret_cast<float4*>(&Yl[off]) = *reinterpret_cast<const float4*>(l8);
        }
    } else {
        __half* Tv = g_vt16 + (size_t)b * CH * HW;
        #pragma unroll
        for (int j = 0; j < 8; j++) {
            int c = a0 + tx * 8 + j;
            __align__(16) __half h8[8];
            #pragma unroll
            for (int i = 0; i < 8; i++)
                h8[i] = __float2half_rn(acc[i][j] + bb[j]);
            size_t off = (size_t)c * HW + n0 + ty * 8;
            *reinterpret_cast<float4*>(&Tv[off]) = *reinterpret_cast<const float4*>(h8);
        }
    }
}

// ---------------------------------------------------------------------------
// K2: S = Q K^T (bf16 split, 3 products). Tile 128x128, K=512 (16 stages of 32).
// ---------------------------------------------------------------------------
__global__ __launch_bounds__(256) void k_scores_mma()
{
    MMA_PROLOG();
    bf16* sm = reinterpret_cast<bf16*>(smc);
    int b = blockIdx.z;
    int m0 = blockIdx.x * 128;
    int n0 = blockIdx.y * 128;

    const bf16* Ah = g_qh + ((size_t)b * HW + n0) * AD;
    const bf16* Al = g_ql + ((size_t)b * HW + n0) * AD;
    const bf16* Bh = g_kh + ((size_t)b * HW + m0) * AD;
    const bf16* Bl = g_kl + ((size_t)b * HW + m0) * AD;

    stage_load32(sb, 0, Ah, Al, Bh, Bl, AD, AD, 0, tid);
    const int KS = AD / 32;
    for (int s = 0; s < KS; s++) {
        cp_wait0();
        __syncthreads();
        if (s + 1 < KS)
            stage_load32(sb, (s + 1) & 1, Ah, Al, Bh, Bl, AD, AD, (s + 1) * 32, tid);
        stage_mma32(sm + (s & 1) * STAGE_H, acc, wm, wn, g, tg);
    }

    float* Sb = g_S + (size_t)b * HW * HW;
    #pragma unroll
    for (int i = 0; i < 4; i++) {
        int n = n0 + wm * 64 + i * 16 + g;
        #pragma unroll
        for (int j = 0; j < 4; j++) {
            int m = m0 + wn * 32 + j * 8 + tg * 2;
            *reinterpret_cast<float2*>(&Sb[(size_t)n * HW + m]) =
                make_float2(acc[i][j][0], acc[i][j][1]);
            *reinterpret_cast<float2*>(&Sb[(size_t)(n + 8) * HW + m]) =
                make_float2(acc[i][j][2], acc[i][j][3]);
        }
    }
}

// ---------------------------------------------------------------------------
// K3: column softmax (axis=-2); reads S fp32, writes P fp16.
// ---------------------------------------------------------------------------
__global__ __launch_bounds__(256) void k_softmax()
{
    int b = blockIdx.y;
    int col = threadIdx.x & 63;
    int m = blockIdx.x * 64 + col;
    int rq = threadIdx.x >> 6;
    const float* Sb = g_S + (size_t)b * HW * HW;
    __half* Pb = g_p16 + (size_t)b * HW * HW;

    int nbeg = rq * (HW / 4), nend = nbeg + (HW / 4);

    float mx = -3.4e38f, den = 0.f;
    for (int n = nbeg; n < nend; n += 8) {
        float v[8];
        #pragma unroll
        for (int u = 0; u < 8; u++) v[u] = Sb[(size_t)(n + u) * HW + m];
        #pragma unroll
        for (int u = 0; u < 8; u++) {
            float val = v[u];
            if (val > mx) { den = den * fast_exp_neg(mx - val) + 1.0f; mx = val; }
            else          { den += fast_exp_neg(val - mx); }
        }
    }

    __shared__ float smx[256], sden[256];
    __shared__ float cmx[64], cinv[64];
    smx[threadIdx.x] = mx; sden[threadIdx.x] = den;
    __syncthreads();
    if (threadIdx.x < 64) {
        float M = smx[threadIdx.x], D = sden[threadIdx.x];
        #pragma unroll
        for (int k = 1; k < 4; k++) {
            float m2 = smx[threadIdx.x + 64 * k], d2 = sden[threadIdx.x + 64 * k];
            float nm = fmaxf(M, m2);
            D = D * fast_exp_neg(M - nm) + d2 * fast_exp_neg(m2 - nm);
            M = nm;
        }
        cmx[threadIdx.x] = M;
        cinv[threadIdx.x] = 1.0f / D;
    }
    __syncthreads();
    float M = cmx[col], inv = cinv[col];

    for (int n = nbeg; n < nend; n += 8) {
        float v[8];
        #pragma unroll
        for (int u = 0; u < 8; u++) v[u] = Sb[(size_t)(n + u) * HW + m];
        #pragma unroll
        for (int u = 0; u < 8; u++)
            Pb[(size_t)(n + u) * HW + m] = __float2half_rn(fast_exp_neg(v[u] - M) * inv);
    }
}

// ---------------------------------------------------------------------------
// K4: O = P V (fp16 single product) + residual. Tile 128(n) x 128(c), K=4096,
// 128 stages of 32, 4-deep cp.async pipeline (wait_group 2).
// ---------------------------------------------------------------------------
__global__ __launch_bounds__(256) void k_out_mma(
    const float* __restrict__ x, float* __restrict__ out)
{
    MMA_PROLOG();
    __half* sm = reinterpret_cast<__half*>(smc);
    int b = blockIdx.z;
    int c0 = blockIdx.x * 128;
    int n0 = blockIdx.y * 128;

    const __half* A = g_p16 + (size_t)b * HW * HW + (size_t)n0 * HW;
    const __half* B = g_vt16 + ((size_t)b * CH + c0) * HW;

    stage_load_o(sb, 0, A, B, HW, HW, 0, tid);
    stage_load_o(sb, 1, A, B, HW, HW, 32, tid);
    stage_load_o(sb, 2, A, B, HW, HW, 64, tid);
    const int KS = HW / 32;
    for (int s = 0; s < KS; s++) {
        cp_wait2();
        __syncthreads();
        if (s + 3 < KS)
            stage_load_o(sb, (s + 3) & 3, A, B, HW, HW, (s + 3) * 32, tid);
        else
            cp_commit();
        stage_mma_o(sm + (s & 3) * OT_STAGE_H, acc, wm, wn, g, tg);
    }

    const float* xb = x + (size_t)b * CH * HW;
    float* ob = out + (size_t)b * CH * HW;
    #pragma unroll
    for (int i = 0; i < 4; i++) {
        int n = n0 + wm * 64 + i * 16 + g;
        #pragma unroll
        for (int j = 0; j < 4; j++) {
            int c = c0 + wn * 32 + j * 8 + tg * 2;
            {
                size_t off = (size_t)n * CH + c;
                float2 xv = *reinterpret_cast<const float2*>(&xb[off]);
                *reinterpret_cast<float2*>(&ob[off]) =
                    make_float2(fmaf(0.1f, acc[i][j][0], xv.x),
                                fmaf(0.1f, acc[i][j][1], xv.y));
            }
            {
                size_t off = (size_t)(n + 8) * CH + c;
                float2 xv = *reinterpret_cast<const float2*>(&xb[off]);
                *reinterpret_cast<float2*>(&ob[off]) =
                    make_float2(fmaf(0.1f, acc[i][j][2], xv.x),
                                fmaf(0.1f, acc[i][j][3], xv.y));
            }
        }
    }
}

// ---------------------------------------------------------------------------
extern "C" void kernel_launch(void* const* d_in, const int* in_sizes, int n_in,
                              void* d_out, int out_size)
{
    const float* x  = (const float*)d_in[0];
    const float* Wq = (const float*)d_in[1];
    const float* bq = (const float*)d_in[2];
    const float* Wk = (const float*)d_in[3];
    const float* bk = (const float*)d_in[4];
    const float* Wv = (const float*)d_in[5];
    const float* bv = (const float*)d_in[6];
    float* out = (float*)d_out;

    static int configured = 0;
    if (!configured) {
        cudaFuncSetAttribute(k_scores_mma, cudaFuncAttributeMaxDynamicSharedMemorySize, SMEM_GEMM);
        cudaFuncSetAttribute(k_out_mma,    cudaFuncAttributeMaxDynamicSharedMemorySize, OT_SMEM);
        configured = 1;
    }

    k_proj      <<<dim3(HW / BM, AD / BN, BATCH * 3), 256>>>(x, Wq, bq, Wk, bk, Wv, bv);
    k_scores_mma<<<dim3(HW / 128, HW / 128, BATCH), 256, SMEM_GEMM>>>();
    k_softmax   <<<dim3(HW / 64, BATCH), 256>>>();
    k_out_mma   <<<dim3(CH / 128, HW / 128, BATCH), 256, OT_SMEM>>>(x, out);
}

// round 8
// speedup vs baseline: 1.5975x; 1.1534x over previous
#include <cuda_runtime.h>
#include <cuda_bf16.h>
#include <cuda_fp16.h>
#include <cstdint>

#define BATCH 4
#define CH    512
#define HW    4096
#define AD    512

typedef __nv_bfloat16 bf16;

// ---------------- scratch (__device__ globals; no allocation) ---------------
__device__ bf16 g_xth[BATCH * HW * CH];          // x^T [b][n][c] hi
__device__ bf16 g_xtl[BATCH * HW * CH];          // lo
__device__ bf16 g_wh[3 * AD * CH];               // Wq,Wk,Wv hi
__device__ bf16 g_wl[3 * AD * CH];               // lo
__device__ bf16 g_qh[BATCH * HW * AD];
__device__ bf16 g_ql[BATCH * HW * AD];
__device__ bf16 g_kh[BATCH * HW * AD];
__device__ bf16 g_kl[BATCH * HW * AD];
__device__ __half g_vt16[BATCH * CH * HW];       // v^T [b][c][n], fp16
__device__ float g_S[(size_t)BATCH * HW * HW];   // scores fp32
__device__ __half g_p16[(size_t)BATCH * HW * HW]; // softmax probs fp16

// ---------------- helpers ----------------------------------------------------
__device__ __forceinline__ uint32_t smem_u32(const void* p) {
    uint32_t a;
    asm("{ .reg .u64 t; cvta.to.shared.u64 t, %1; cvt.u32.u64 %0, t; }" : "=r"(a) : "l"(p));
    return a;
}
__device__ __forceinline__ void cp16(uint32_t d, const void* s) {
    asm volatile("cp.async.ca.shared.global [%0], [%1], 16;" :: "r"(d), "l"(s));
}
__device__ __forceinline__ void cp_commit() { asm volatile("cp.async.commit_group;" ::: "memory"); }
__device__ __forceinline__ void cp_wait0()  { asm volatile("cp.async.wait_group 0;" ::: "memory"); }
__device__ __forceinline__ void cp_wait2()  { asm volatile("cp.async.wait_group 2;" ::: "memory"); }

__device__ __forceinline__ uint32_t lds32(const bf16* base, int halfoff) {
    return *reinterpret_cast<const uint32_t*>(base + halfoff);
}
__device__ __forceinline__ uint32_t lds32h(const __half* base, int halfoff) {
    return *reinterpret_cast<const uint32_t*>(base + halfoff);
}

__device__ __forceinline__ void mma16816(float* c,
    uint32_t a0, uint32_t a1, uint32_t a2, uint32_t a3, uint32_t b0, uint32_t b1)
{
    asm volatile(
        "mma.sync.aligned.m16n8k16.row.col.f32.bf16.bf16.f32 "
        "{%0,%1,%2,%3},{%4,%5,%6,%7},{%8,%9},{%0,%1,%2,%3};"
        : "+f"(c[0]), "+f"(c[1]), "+f"(c[2]), "+f"(c[3])
        : "r"(a0), "r"(a1), "r"(a2), "r"(a3), "r"(b0), "r"(b1));
}
__device__ __forceinline__ void mma16816h(float* c,
    uint32_t a0, uint32_t a1, uint32_t a2, uint32_t a3, uint32_t b0, uint32_t b1)
{
    asm volatile(
        "mma.sync.aligned.m16n8k16.row.col.f32.f16.f16.f32 "
        "{%0,%1,%2,%3},{%4,%5,%6,%7},{%8,%9},{%0,%1,%2,%3};"
        : "+f"(c[0]), "+f"(c[1]), "+f"(c[2]), "+f"(c[3])
        : "r"(a0), "r"(a1), "r"(a2), "r"(a3), "r"(b0), "r"(b1));
}

// FMA-only exp (x <= 0)
__device__ __forceinline__ float fast_exp_neg(float x) {
    float t = x * 1.4426950408889634f;
    t = fmaxf(t, -126.0f);
    float r = rintf(t);
    float f = t - r;
    float p = 1.3333558e-3f;
    p = fmaf(p, f, 9.6181291e-3f);
    p = fmaf(p, f, 5.5504110e-2f);
    p = fmaf(p, f, 2.4022651e-1f);
    p = fmaf(p, f, 6.9314718e-1f);
    p = fmaf(p, f, 1.0f);
    return __int_as_float(__float_as_int(p) + ((int)r << 23));
}

__device__ __forceinline__ void split2(float v, bf16& h, bf16& l) {
    h = __float2bfloat16(v);
    l = __float2bfloat16(v - __bfloat162float(h));
}

// ---------------- split-GEMM smem layout: K=32 stages, double-buffered -------
#define TT      40
#define TILE_H  5120
#define TILE_B  10240
#define STAGE_H 20480
#define STAGE_B 40960
#define SMEM_GEMM (2 * STAGE_B)   // 81920

__device__ __forceinline__ void stage_load32(uint32_t sb, int st,
    const bf16* __restrict__ Ah, const bf16* __restrict__ Al,
    const bf16* __restrict__ Bh, const bf16* __restrict__ Bl,
    int ldA, int ldB, int k0, int tid)
{
    int row = tid >> 1;
    int h0  = (tid & 1) * 16;
    uint32_t d = sb + st * STAGE_B + row * 80 + h0 * 2;
    const size_t oA = (size_t)row * ldA + k0 + h0;
    const size_t oB = (size_t)row * ldB + k0 + h0;
    cp16(d + 0 * TILE_B,      Ah + oA); cp16(d + 0 * TILE_B + 16, Ah + oA + 8);
    cp16(d + 1 * TILE_B,      Al + oA); cp16(d + 1 * TILE_B + 16, Al + oA + 8);
    cp16(d + 2 * TILE_B,      Bh + oB); cp16(d + 2 * TILE_B + 16, Bh + oB + 8);
    cp16(d + 3 * TILE_B,      Bl + oB); cp16(d + 3 * TILE_B + 16, Bl + oB + 8);
    cp_commit();
}

__device__ __forceinline__ void stage_mma32(const bf16* smst, float acc[4][4][4],
                                            int wm, int wn, int g, int tg)
{
    const bf16* sAh = smst;
    const bf16* sAl = smst + TILE_H;
    const bf16* sBh = smst + 2 * TILE_H;
    const bf16* sBl = smst + 3 * TILE_H;

    #pragma unroll
    for (int kh = 0; kh < 2; kh++) {
        int ko = kh * 16;
        uint32_t ah[4][4], bh[4][2];
        #pragma unroll
        for (int i = 0; i < 4; i++) {
            int r = wm * 64 + i * 16 + g;
            ah[i][0] = lds32(sAh, r * TT + ko + tg * 2);
            ah[i][1] = lds32(sAh, (r + 8) * TT + ko + tg * 2);
            ah[i][2] = lds32(sAh, r * TT + ko + tg * 2 + 8);
            ah[i][3] = lds32(sAh, (r + 8) * TT + ko + tg * 2 + 8);
        }
        #pragma unroll
        for (int j = 0; j < 4; j++) {
            int r = wn * 32 + j * 8 + g;
            bh[j][0] = lds32(sBh, r * TT + ko + tg * 2);
            bh[j][1] = lds32(sBh, r * TT + ko + tg * 2 + 8);
        }
        #pragma unroll
        for (int i = 0; i < 4; i++)
            #pragma unroll
            for (int j = 0; j < 4; j++)
                mma16816(acc[i][j], ah[i][0], ah[i][1], ah[i][2], ah[i][3], bh[j][0], bh[j][1]);

        uint32_t bl[4][2];
        #pragma unroll
        for (int j = 0; j < 4; j++) {
            int r = wn * 32 + j * 8 + g;
            bl[j][0] = lds32(sBl, r * TT + ko + tg * 2);
            bl[j][1] = lds32(sBl, r * TT + ko + tg * 2 + 8);
        }
        #pragma unroll
        for (int i = 0; i < 4; i++)
            #pragma unroll
            for (int j = 0; j < 4; j++)
                mma16816(acc[i][j], ah[i][0], ah[i][1], ah[i][2], ah[i][3], bl[j][0], bl[j][1]);

        uint32_t al[4][4];
        #pragma unroll
        for (int i = 0; i < 4; i++) {
            int r = wm * 64 + i * 16 + g;
            al[i][0] = lds32(sAl, r * TT + ko + tg * 2);
            al[i][1] = lds32(sAl, (r + 8) * TT + ko + tg * 2);
            al[i][2] = lds32(sAl, r * TT + ko + tg * 2 + 8);
            al[i][3] = lds32(sAl, (r + 8) * TT + ko + tg * 2 + 8);
        }
        #pragma unroll
        for (int i = 0; i < 4; i++)
            #pragma unroll
            for (int j = 0; j < 4; j++)
                mma16816(acc[i][j], al[i][0], al[i][1], al[i][2], al[i][3], bh[j][0], bh[j][1]);
    }
}

#define MMA_PROLOG()                                                             \
    extern __shared__ char smc[];                                                \
    uint32_t sb = smem_u32(smc);                                                 \
    int tid = threadIdx.x, lane = tid & 31, wid = tid >> 5;                      \
    int wm = wid & 1, wn = wid >> 1, g = lane >> 2, tg = lane & 3;               \
    float acc[4][4][4];                                                          \
    _Pragma("unroll")                                                            \
    for (int i = 0; i < 4; i++)                                                  \
        _Pragma("unroll")                                                        \
        for (int j = 0; j < 4; j++)                                              \
            _Pragma("unroll")                                                    \
            for (int r = 0; r < 4; r++) acc[i][j][r] = 0.f;

#define MMA_MAINLOOP_SPLIT(Ah, Al, Bh, Bl, ldA, ldB, KS)                         \
    stage_load32(sb, 0, Ah, Al, Bh, Bl, ldA, ldB, 0, tid);                       \
    for (int s = 0; s < (KS); s++) {                                             \
        cp_wait0();                                                              \
        __syncthreads();                                                         \
        if (s + 1 < (KS))                                                        \
            stage_load32(sb, (s + 1) & 1, Ah, Al, Bh, Bl, ldA, ldB,              \
                         (s + 1) * 32, tid);                                     \
        stage_mma32(reinterpret_cast<bf16*>(smc) + (s & 1) * STAGE_H,            \
                    acc, wm, wn, g, tg);                                         \
    }

// ---------------- k_out smem layout: fp16, 2 tiles, 4-deep pipeline ----------
#define OT_TILE_H  5120
#define OT_TILE_B  10240
#define OT_STAGE_H 10240
#define OT_STAGE_B 20480
#define OT_SMEM    (4 * OT_STAGE_B)   // 81920

__device__ __forceinline__ void stage_load_o(uint32_t sb, int st,
    const __half* __restrict__ A, const __half* __restrict__ B,
    int ldA, int ldB, int k0, int tid)
{
    int row = tid >> 1;
    int h0  = (tid & 1) * 16;
    uint32_t d = sb + st * OT_STAGE_B + row * 80 + h0 * 2;
    const size_t oA = (size_t)row * ldA + k0 + h0;
    const size_t oB = (size_t)row * ldB + k0 + h0;
    cp16(d,                  A + oA); cp16(d + 16,              A + oA + 8);
    cp16(d + OT_TILE_B,      B + oB); cp16(d + OT_TILE_B + 16,  B + oB + 8);
    cp_commit();
}

__device__ __forceinline__ void stage_mma_o(const __half* smst, float acc[4][4][4],
                                            int wm, int wn, int g, int tg)
{
    const __half* sA = smst;
    const __half* sB = smst + OT_TILE_H;

    #pragma unroll
    for (int kh = 0; kh < 2; kh++) {
        int ko = kh * 16;
        uint32_t a[4][4], b[4][2];
        #pragma unroll
        for (int i = 0; i < 4; i++) {
            int r = wm * 64 + i * 16 + g;
            a[i][0] = lds32h(sA, r * TT + ko + tg * 2);
            a[i][1] = lds32h(sA, (r + 8) * TT + ko + tg * 2);
            a[i][2] = lds32h(sA, r * TT + ko + tg * 2 + 8);
            a[i][3] = lds32h(sA, (r + 8) * TT + ko + tg * 2 + 8);
        }
        #pragma unroll
        for (int j = 0; j < 4; j++) {
            int r = wn * 32 + j * 8 + g;
            b[j][0] = lds32h(sB, r * TT + ko + tg * 2);
            b[j][1] = lds32h(sB, r * TT + ko + tg * 2 + 8);
        }
        #pragma unroll
        for (int i = 0; i < 4; i++)
            #pragma unroll
            for (int j = 0; j < 4; j++)
                mma16816h(acc[i][j], a[i][0], a[i][1], a[i][2], a[i][3], b[j][0], b[j][1]);
    }
}

// ---------------------------------------------------------------------------
// K0a: x [b][c][n] -> transposed split xt hi/lo [b][n][c]
// ---------------------------------------------------------------------------
__global__ __launch_bounds__(256) void k_split_x(const float* __restrict__ x)
{
    __shared__ float t[32][33];
    int b = blockIdx.z;
    int n0 = blockIdx.x * 32, c0 = blockIdx.y * 32;
    int tx = threadIdx.x & 31, ty = threadIdx.x >> 5;   // 32 x 8

    const float* xb = x + (size_t)b * CH * HW;
    #pragma unroll
    for (int k = 0; k < 4; k++)
        t[ty + 8 * k][tx] = xb[(size_t)(c0 + ty + 8 * k) * HW + n0 + tx];
    __syncthreads();
    bf16* Xh = g_xth + (size_t)b * HW * CH;
    bf16* Xl = g_xtl + (size_t)b * HW * CH;
    #pragma unroll
    for (int k = 0; k < 4; k++) {
        float v = t[tx][ty + 8 * k];
        bf16 h, l; split2(v, h, l);
        size_t off = (size_t)(n0 + ty + 8 * k) * CH + c0 + tx;
        Xh[off] = h; Xl[off] = l;
    }
}

// K0b: split Wq,Wk,Wv into g_wh/g_wl
__global__ __launch_bounds__(256) void k_split_w(
    const float* __restrict__ Wq, const float* __restrict__ Wk, const float* __restrict__ Wv)
{
    int idx = blockIdx.x * 256 + threadIdx.x;
    int p = blockIdx.y;
    const float* W = (p == 0) ? Wq : ((p == 1) ? Wk : Wv);
    float v = W[idx];
    bf16 h, l; split2(v, h, l);
    g_wh[p * AD * CH + idx] = h;
    g_wl[p * AD * CH + idx] = l;
}

// ---------------------------------------------------------------------------
// K1: projections via split MMA. Y[n,a] = sum_c xt[n,c] W[a,c] + bias.
// q,k epilogue: smem bounce -> coalesced [n][a] split stores.
// v epilogue:   smem bounce -> coalesced transposed [c][n] fp16 stores.
// ---------------------------------------------------------------------------
__global__ __launch_bounds__(256) void k_proj_mma(
    const float* __restrict__ bq, const float* __restrict__ bk, const float* __restrict__ bv)
{
    MMA_PROLOG();
    int z = blockIdx.z;
    int b = z / 3, p = z % 3;
    int n0 = blockIdx.x * 128;
    int a0 = blockIdx.y * 128;

    const bf16* Ah = g_xth + ((size_t)b * HW + n0) * CH;
    const bf16* Al = g_xtl + ((size_t)b * HW + n0) * CH;
    const bf16* Bh = g_wh + (size_t)p * AD * CH + (size_t)a0 * CH;
    const bf16* Bl = g_wl + (size_t)p * AD * CH + (size_t)a0 * CH;
    const float* bias = (p == 0) ? bq : ((p == 1) ? bk : bv);

    MMA_MAINLOOP_SPLIT(Ah, Al, Bh, Bl, CH, CH, CH / 32);

    __syncthreads();   // mainloop smem dead; reuse as bounce buffer

    if (p < 2) {
        // bounce [n-local][a-local] with row stride 136 halves
        bf16* th = reinterpret_cast<bf16*>(smc);
        bf16* tl = th + 128 * 136;
        #pragma unroll
        for (int j = 0; j < 4; j++) {
            int c2 = wn * 32 + j * 8 + tg * 2;
            float bb0 = bias[a0 + c2], bb1 = bias[a0 + c2 + 1];
            #pragma unroll
            for (int i = 0; i < 4; i++) {
                int nr = wm * 64 + i * 16 + g;
                #pragma unroll
                for (int half = 0; half < 2; half++) {
                    int nn = nr + half * 8;
                    float v0 = acc[i][j][half * 2 + 0] + bb0;
                    float v1 = acc[i][j][half * 2 + 1] + bb1;
                    bf16 h0, l0, h1, l1;
                    split2(v0, h0, l0); split2(v1, h1, l1);
                    __nv_bfloat162 hh; hh.x = h0; hh.y = h1;
                    __nv_bfloat162 ll; ll.x = l0; ll.y = l1;
                    *reinterpret_cast<__nv_bfloat162*>(&th[nn * 136 + c2]) = hh;
                    *reinterpret_cast<__nv_bfloat162*>(&tl[nn * 136 + c2]) = ll;
                }
            }
        }
        __syncthreads();
        bf16* Yh = ((p == 0) ? g_qh : g_kh) + (size_t)b * HW * AD;
        bf16* Yl = ((p == 0) ? g_ql : g_kl) + (size_t)b * HW * AD;
        int r = tid >> 1, part = tid & 1;
        size_t off = (size_t)(n0 + r) * AD + a0 + part * 64;
        const float4* sh4 = reinterpret_cast<const float4*>(th + r * 136 + part * 64);
        const float4* sl4 = reinterpret_cast<const float4*>(tl + r * 136 + part * 64);
        float4* dh4 = reinterpret_cast<float4*>(Yh + off);
        float4* dl4 = reinterpret_cast<float4*>(Yl + off);
        #pragma unroll
        for (int u = 0; u < 8; u++) { dh4[u] = sh4[u]; dl4[u] = sl4[u]; }
    } else {
        // bounce transposed [c-local][n-local], fp16
        __half* th = reinterpret_cast<__half*>(smc);
        #pragma unroll
        for (int j = 0; j < 4; j++) {
            int c2 = wn * 32 + j * 8 + tg * 2;
            float bb0 = bias[a0 + c2], bb1 = bias[a0 + c2 + 1];
            #pragma unroll
            for (int i = 0; i < 4; i++) {
                int nr = wm * 64 + i * 16 + g;
                #pragma unroll
                for (int half = 0; half < 2; half++) {
                    int nn = nr + half * 8;
                    th[(c2 + 0) * 136 + nn] = __float2half_rn(acc[i][j][half * 2 + 0] + bb0);
                    th[(c2 + 1) * 136 + nn] = __float2half_rn(acc[i][j][half * 2 + 1] + bb1);
                }
            }
        }
        __syncthreads();
        __half* Tv = g_vt16 + (size_t)b * CH * HW;
        int r = tid >> 1, part = tid & 1;
        size_t off = (size_t)(a0 + r) * HW + n0 + part * 64;
        const float4* sh4 = reinterpret_cast<const float4*>(th + r * 136 + part * 64);
        float4* dh4 = reinterpret_cast<float4*>(Tv + off);
        #pragma unroll
        for (int u = 0; u < 8; u++) dh4[u] = sh4[u];
    }
}

// ---------------------------------------------------------------------------
// K2: S = Q K^T (bf16 split, 3 products). Tile 128x128, K=512 (16 stages of 32).
// ---------------------------------------------------------------------------
__global__ __launch_bounds__(256) void k_scores_mma()
{
    MMA_PROLOG();
    int b = blockIdx.z;
    int m0 = blockIdx.x * 128;
    int n0 = blockIdx.y * 128;

    const bf16* Ah = g_qh + ((size_t)b * HW + n0) * AD;
    const bf16* Al = g_ql + ((size_t)b * HW + n0) * AD;
    const bf16* Bh = g_kh + ((size_t)b * HW + m0) * AD;
    const bf16* Bl = g_kl + ((size_t)b * HW + m0) * AD;

    MMA_MAINLOOP_SPLIT(Ah, Al, Bh, Bl, AD, AD, AD / 32);

    float* Sb = g_S + (size_t)b * HW * HW;
    #pragma unroll
    for (int i = 0; i < 4; i++) {
        int n = n0 + wm * 64 + i * 16 + g;
        #pragma unroll
        for (int j = 0; j < 4; j++) {
            int m = m0 + wn * 32 + j * 8 + tg * 2;
            *reinterpret_cast<float2*>(&Sb[(size_t)n * HW + m]) =
                make_float2(acc[i][j][0], acc[i][j][1]);
            *reinterpret_cast<float2*>(&Sb[(size_t)(n + 8) * HW + m]) =
                make_float2(acc[i][j][2], acc[i][j][3]);
        }
    }
}

// ---------------------------------------------------------------------------
// K3: column softmax (axis=-2); reads S fp32, writes P fp16.
// ---------------------------------------------------------------------------
__global__ __launch_bounds__(256) void k_softmax()
{
    int b = blockIdx.y;
    int col = threadIdx.x & 63;
    int m = blockIdx.x * 64 + col;
    int rq = threadIdx.x >> 6;
    const float* Sb = g_S + (size_t)b * HW * HW;
    __half* Pb = g_p16 + (size_t)b * HW * HW;

    int nbeg = rq * (HW / 4), nend = nbeg + (HW / 4);

    float mx = -3.4e38f, den = 0.f;
    for (int n = nbeg; n < nend; n += 8) {
        float v[8];
        #pragma unroll
        for (int u = 0; u < 8; u++) v[u] = Sb[(size_t)(n + u) * HW + m];
        #pragma unroll
        for (int u = 0; u < 8; u++) {
            float val = v[u];
            if (val > mx) { den = den * fast_exp_neg(mx - val) + 1.0f; mx = val; }
            else          { den += fast_exp_neg(val - mx); }
        }
    }

    __shared__ float smx[256], sden[256];
    __shared__ float cmx[64], cinv[64];
    smx[threadIdx.x] = mx; sden[threadIdx.x] = den;
    __syncthreads();
    if (threadIdx.x < 64) {
        float M = smx[threadIdx.x], D = sden[threadIdx.x];
        #pragma unroll
        for (int k = 1; k < 4; k++) {
            float m2 = smx[threadIdx.x + 64 * k], d2 = sden[threadIdx.x + 64 * k];
            float nm = fmaxf(M, m2);
            D = D * fast_exp_neg(M - nm) + d2 * fast_exp_neg(m2 - nm);
            M = nm;
        }
        cmx[threadIdx.x] = M;
        cinv[threadIdx.x] = 1.0f / D;
    }
    __syncthreads();
    float M = cmx[col], inv = cinv[col];

    for (int n = nbeg; n < nend; n += 8) {
        float v[8];
        #pragma unroll
        for (int u = 0; u < 8; u++) v[u] = Sb[(size_t)(n + u) * HW + m];
        #pragma unroll
        for (int u = 0; u < 8; u++)
            Pb[(size_t)(n + u) * HW + m] = __float2half_rn(fast_exp_neg(v[u] - M) * inv);
    }
}

// ---------------------------------------------------------------------------
// K4: O = P V (fp16 single product) + residual. K=4096, 128 stages of 32,
// 4-deep cp.async pipeline (wait_group 2).
// ---------------------------------------------------------------------------
__global__ __launch_bounds__(256) void k_out_mma(
    const float* __restrict__ x, float* __restrict__ out)
{
    MMA_PROLOG();
    __half* sm = reinterpret_cast<__half*>(smc);
    int b = blockIdx.z;
    int c0 = blockIdx.x * 128;
    int n0 = blockIdx.y * 128;

    const __half* A = g_p16 + (size_t)b * HW * HW + (size_t)n0 * HW;
    const __half* B = g_vt16 + ((size_t)b * CH + c0) * HW;

    stage_load_o(sb, 0, A, B, HW, HW, 0, tid);
    stage_load_o(sb, 1, A, B, HW, HW, 32, tid);
    stage_load_o(sb, 2, A, B, HW, HW, 64, tid);
    const int KS = HW / 32;
    for (int s = 0; s < KS; s++) {
        cp_wait2();
        __syncthreads();
        if (s + 3 < KS)
            stage_load_o(sb, (s + 3) & 3, A, B, HW, HW, (s + 3) * 32, tid);
        else
            cp_commit();
        stage_mma_o(sm + (s & 3) * OT_STAGE_H, acc, wm, wn, g, tg);
    }

    const float* xb = x + (size_t)b * CH * HW;
    float* ob = out + (size_t)b * CH * HW;
    #pragma unroll
    for (int i = 0; i < 4; i++) {
        int n = n0 + wm * 64 + i * 16 + g;
        #pragma unroll
        for (int j = 0; j < 4; j++) {
            int c = c0 + wn * 32 + j * 8 + tg * 2;
            {
                size_t off = (size_t)n * CH + c;
                float2 xv = *reinterpret_cast<const float2*>(&xb[off]);
                *reinterpret_cast<float2*>(&ob[off]) =
                    make_float2(fmaf(0.1f, acc[i][j][0], xv.x),
                                fmaf(0.1f, acc[i][j][1], xv.y));
            }
            {
                size_t off = (size_t)(n + 8) * CH + c;
                float2 xv = *reinterpret_cast<const float2*>(&xb[off]);
                *reinterpret_cast<float2*>(&ob[off]) =
                    make_float2(fmaf(0.1f, acc[i][j][2], xv.x),
                                fmaf(0.1f, acc[i][j][3], xv.y));
            }
        }
    }
}

// ---------------------------------------------------------------------------
extern "C" void kernel_launch(void* const* d_in, const int* in_sizes, int n_in,
                              void* d_out, int out_size)
{
    const float* x  = (const float*)d_in[0];
    const float* Wq = (const float*)d_in[1];
    const float* bq = (const float*)d_in[2];
    const float* Wk = (const float*)d_in[3];
    const float* bk = (const float*)d_in[4];
    const float* Wv = (const float*)d_in[5];
    const float* bv = (const float*)d_in[6];
    float* out = (float*)d_out;

    static int configured = 0;
    if (!configured) {
        cudaFuncSetAttribute(k_proj_mma,   cudaFuncAttributeMaxDynamicSharedMemorySize, SMEM_GEMM);
        cudaFuncSetAttribute(k_scores_mma, cudaFuncAttributeMaxDynamicSharedMemorySize, SMEM_GEMM);
        cudaFuncSetAttribute(k_out_mma,    cudaFuncAttributeMaxDynamicSharedMemorySize, OT_SMEM);
        configured = 1;
    }

    k_split_x   <<<dim3(HW / 32, CH / 32, BATCH), 256>>>(x);
    k_split_w   <<<dim3(AD * CH / 256, 3), 256>>>(Wq, Wk, Wv);
    k_proj_mma  <<<dim3(HW / 128, AD / 128, BATCH * 3), 256, SMEM_GEMM>>>(bq, bk, bv);
    k_scores_mma<<<dim3(HW / 128, HW / 128, BATCH), 256, SMEM_GEMM>>>();
    k_softmax   <<<dim3(HW / 64, BATCH), 256>>>();
    k_out_mma   <<<dim3(CH / 128, HW / 128, BATCH), 256, OT_SMEM>>>(x, out);
}